// round 1
// baseline (speedup 1.0000x reference)
#include <cuda_runtime.h>
#include <math.h>
#include <float.h>

#define BB   8
#define NN   512
#define CC   256
#define HE   32
#define F0   64
#define OUTD 2

// ---------------- scratch (device globals; no allocations) ----------------
__device__ float g_xa[BB*NN*HE];
__device__ float g_xb[BB*NN*HE];
__device__ float g_e [BB*NN*NN];          // 8 MB
__device__ float g_L0[BB*NN*NN];          // 8 MB
__device__ float g_L1[BB*NN*NN];          // 8 MB (holds A_pred, then L1 in-place)
__device__ float g_D0[BB*NN];
__device__ float g_D1[BB*NN];
__device__ float g_xh[BB*NN*2*CC];        // 8 MB (layer0 needs (B,N,512))
__device__ float g_h0[BB*NN*F0];
__device__ float g_h1[BB*NN*F0];

// ---------------- xa = x@ew1[:C], xb = x@ew1[C:] ----------------
__global__ __launch_bounds__(64) void k_xaxb(const float* __restrict__ x,
                                             const float* __restrict__ ew1) {
    int row = blockIdx.x;            // b*N + i
    int t = threadIdx.x;             // 0..63
    __shared__ float xs[CC];
    for (int c = t; c < CC; c += 64) xs[c] = x[row*CC + c];
    __syncthreads();
    int k = t & 31;
    const float* w = ew1 + (t < 32 ? 0 : CC*HE) + k;
    float acc = 0.f;
#pragma unroll 8
    for (int c = 0; c < CC; ++c) acc = fmaf(xs[c], w[c*HE], acc);
    float* dst = (t < 32) ? g_xa : g_xb;
    dst[row*HE + k] = acc;
}

// ---------------- e[b,i,j] = sum_k relu(xa_i+xb_j+eb1)*ew2 + eb2 ----------------
__global__ __launch_bounds__(256) void k_edge(const float* __restrict__ ew2,
                                              const float* __restrict__ eb1,
                                              const float* __restrict__ eb2) {
    int j0 = blockIdx.x*32, i0 = blockIdx.y*32, b = blockIdx.z;
    __shared__ float xas[32][33], xbs[32][33], w[32], b1[32];
    int t = threadIdx.y*32 + threadIdx.x;
    for (int idx = t; idx < 1024; idx += 256) {
        int r = idx >> 5, k = idx & 31;
        xas[r][k] = g_xa[(b*NN + i0 + r)*HE + k];
        xbs[r][k] = g_xb[(b*NN + j0 + r)*HE + k];
    }
    if (t < 32) { w[t] = ew2[t]; b1[t] = eb1[t]; }
    __syncthreads();
    int tx = threadIdx.x;
    float bias2 = eb2[0];
#pragma unroll
    for (int r = 0; r < 4; ++r) {
        int il = threadIdx.y + r*8;
        float acc = bias2;
#pragma unroll
        for (int k = 0; k < 32; ++k) {
            float v = xas[il][k] + xbs[tx][k] + b1[k];
            acc = fmaf(fmaxf(v, 0.f), w[k], acc);
        }
        g_e[(b*NN + i0 + il)*NN + j0 + tx] = acc;
    }
}

// ---------------- A_pred[b,i,j] = (i!=j & valid) ? exp(0.5*(e_ij+e_ji)) : 0 ----------------
__global__ __launch_bounds__(256) void k_apred(const float* __restrict__ mask) {
    int j0 = blockIdx.x*32, i0 = blockIdx.y*32, b = blockIdx.z;
    __shared__ float te[32][33];
    __shared__ float mi_s[32], mj_s[32];
    int t = threadIdx.y*32 + threadIdx.x;
    for (int idx = t; idx < 1024; idx += 256) {
        int r = idx >> 5, c2 = idx & 31;
        te[r][c2] = g_e[(b*NN + j0 + r)*NN + i0 + c2];  // tile of e at (j0,i0)
    }
    if (t < 32) { mi_s[t] = mask[b*NN + i0 + t]; mj_s[t] = mask[b*NN + j0 + t]; }
    __syncthreads();
    int tx = threadIdx.x;
#pragma unroll
    for (int r = 0; r < 4; ++r) {
        int il = threadIdx.y + r*8;
        int gi = i0 + il, gj = j0 + tx;
        float eij = g_e[(b*NN + gi)*NN + gj];
        float eji = te[tx][il];
        float v = 0.f;
        if (gi != gj && mi_s[il] > 0.f && mj_s[tx] > 0.f)
            v = expf(0.5f*(eij + eji));
        g_L1[(b*NN + gi)*NN + gj] = v;   // A_pred stored in L1 buffer
    }
}

// ---------------- D[b,k] = (colsum(A_hat) + 1e-5)^-0.5 (A_hat = A + I) ----------------
__global__ __launch_bounds__(256) void k_colsum(const float* __restrict__ Aext, int which) {
    const float* src = (which == 0) ? Aext : g_L1;
    float* D = (which == 0) ? g_D0 : g_D1;
    int c0 = blockIdx.x*32, b = blockIdx.y;
    int tx = threadIdx.x, ty = threadIdx.y;
    float s = 0.f;
    for (int r = ty; r < NN; r += 8)
        s += src[(b*NN + r)*NN + c0 + tx];
    __shared__ float sm[8][32];
    sm[ty][tx] = s;
    __syncthreads();
    if (ty == 0) {
        float tot = 0.f;
#pragma unroll
        for (int q = 0; q < 8; ++q) tot += sm[q][tx];
        D[b*NN + c0 + tx] = rsqrtf(tot + 1.0f + 1e-5f);
    }
}

// ---------------- L[b,i,j] = D_i * (A + I)_ij * D_j ----------------
__global__ __launch_bounds__(256) void k_scaleL(const float* __restrict__ Aext, int which) {
    int idx = blockIdx.x*256 + threadIdx.x;   // < B*N*N
    int j = idx & (NN-1);
    int i = (idx >> 9) & (NN-1);
    int b = idx >> 18;
    const float* src = (which == 0) ? Aext : g_L1;
    const float* D   = (which == 0) ? g_D0 : g_D1;
    float* out       = (which == 0) ? g_L0 : g_L1;   // which=1 is in-place
    float a = src[idx] + (i == j ? 1.f : 0.f);
    out[idx] = D[b*NN + i] * a * D[b*NN + j];
}

// ---------------- xh[:, s*F : (s+1)*F] = L_s @ H   (per batch b) ----------------
// 64x64 tile, BK=16, 256 threads, TM=TN=4
__global__ __launch_bounds__(256) void k_gemm_LH(const float* __restrict__ xext,
                                                 int hsel, int F) {
    int z = blockIdx.z, b = z >> 1, s = z & 1;
    const float* L = (s ? g_L1 : g_L0) + (size_t)b*NN*NN;
    const float* H = (hsel == 0 ? xext : (hsel == 1 ? g_h0 : g_h1)) + (size_t)b*NN*F;
    float* O = g_xh + (size_t)b*NN*(2*F) + s*F;
    int m0 = blockIdx.y*64, n0 = blockIdx.x*64;

    __shared__ float As[16][64];
    __shared__ float Bs[16][64];
    int t = threadIdx.x;
    int tx = t & 15, ty = t >> 4;
    float acc[4][4] = {};

    for (int k0 = 0; k0 < NN; k0 += 16) {
        {   // A tile: 64 rows x 16 cols of L (store transposed k-major)
            int m = t >> 2, kq = (t & 3)*4;
            float4 v = *(const float4*)&L[(m0+m)*NN + k0 + kq];
            As[kq+0][m] = v.x; As[kq+1][m] = v.y; As[kq+2][m] = v.z; As[kq+3][m] = v.w;
        }
        {   // B tile: 16 rows x 64 cols of H
            int kk = t >> 4, nv = (t & 15)*4;
            *(float4*)&Bs[kk][nv] = *(const float4*)&H[(k0+kk)*F + n0 + nv];
        }
        __syncthreads();
#pragma unroll
        for (int k = 0; k < 16; ++k) {
            float4 a = *(const float4*)&As[k][ty*4];
            float4 bv = *(const float4*)&Bs[k][tx*4];
            float av[4] = {a.x, a.y, a.z, a.w};
            float bb[4] = {bv.x, bv.y, bv.z, bv.w};
#pragma unroll
            for (int u = 0; u < 4; ++u)
#pragma unroll
                for (int v = 0; v < 4; ++v)
                    acc[u][v] = fmaf(av[u], bb[v], acc[u][v]);
        }
        __syncthreads();
    }
#pragma unroll
    for (int u = 0; u < 4; ++u) {
        int m = m0 + ty*4 + u;
        float4 o = make_float4(acc[u][0], acc[u][1], acc[u][2], acc[u][3]);
        *(float4*)&O[(size_t)m*(2*F) + n0 + tx*4] = o;
    }
}

// ---------------- Hout = relu((xh @ W + bias) * mask) ; M=4096, N=64 ----------------
__global__ __launch_bounds__(256) void k_gemm_W(const float* __restrict__ W,
                                                const float* __restrict__ bias,
                                                const float* __restrict__ mask,
                                                int outsel, int K) {
    const float* XH = g_xh;
    float* Hout = outsel ? g_h1 : g_h0;
    int m0 = blockIdx.x*64;

    __shared__ float As[16][64];
    __shared__ float Bs[16][64];
    int t = threadIdx.x;
    int tx = t & 15, ty = t >> 4;
    float acc[4][4] = {};

    for (int k0 = 0; k0 < K; k0 += 16) {
        {
            int m = t >> 2, kq = (t & 3)*4;
            float4 v = *(const float4*)&XH[(size_t)(m0+m)*K + k0 + kq];
            As[kq+0][m] = v.x; As[kq+1][m] = v.y; As[kq+2][m] = v.z; As[kq+3][m] = v.w;
        }
        {
            int kk = t >> 4, nv = (t & 15)*4;
            *(float4*)&Bs[kk][nv] = *(const float4*)&W[(k0+kk)*64 + nv];
        }
        __syncthreads();
#pragma unroll
        for (int k = 0; k < 16; ++k) {
            float4 a = *(const float4*)&As[k][ty*4];
            float4 bv = *(const float4*)&Bs[k][tx*4];
            float av[4] = {a.x, a.y, a.z, a.w};
            float bb[4] = {bv.x, bv.y, bv.z, bv.w};
#pragma unroll
            for (int u = 0; u < 4; ++u)
#pragma unroll
                for (int v = 0; v < 4; ++v)
                    acc[u][v] = fmaf(av[u], bb[v], acc[u][v]);
        }
        __syncthreads();
    }
#pragma unroll
    for (int u = 0; u < 4; ++u) {
        int row = m0 + ty*4 + u;
        float mk = mask[row];
        float o[4];
#pragma unroll
        for (int v = 0; v < 4; ++v) {
            float z = (acc[u][v] + bias[tx*4 + v]) * mk;
            o[v] = fmaxf(z, 0.f);
        }
        *(float4*)&Hout[(size_t)row*64 + tx*4] = make_float4(o[0], o[1], o[2], o[3]);
    }
}

// ---------------- g = max over N; out = g @ fcw + fcb ----------------
__global__ __launch_bounds__(64) void k_final(const float* __restrict__ fcw,
                                              const float* __restrict__ fcb,
                                              float* __restrict__ out) {
    int b = blockIdx.x;
    int f = threadIdx.x;   // 64
    const float* h2 = g_h0;   // layer2 output lives in g_h0
    float m = -FLT_MAX;
    for (int i = 0; i < NN; ++i)
        m = fmaxf(m, h2[((size_t)b*NN + i)*F0 + f]);
    __shared__ float gs[F0];
    gs[f] = m;
    __syncthreads();
    if (f < OUTD) {
        float acc = fcb[f];
#pragma unroll
        for (int q = 0; q < F0; ++q) acc = fmaf(gs[q], fcw[q*OUTD + f], acc);
        out[b*OUTD + f] = acc;
    }
}

// ---------------- launch ----------------
extern "C" void kernel_launch(void* const* d_in, const int* in_sizes, int n_in,
                              void* d_out, int out_size) {
    const float* x    = (const float*)d_in[0];
    const float* A    = (const float*)d_in[1];
    const float* mask = (const float*)d_in[2];
    const float* ew1  = (const float*)d_in[3];
    const float* eb1  = (const float*)d_in[4];
    const float* ew2  = (const float*)d_in[5];
    const float* eb2  = (const float*)d_in[6];
    const float* gw0  = (const float*)d_in[7];
    const float* gb0  = (const float*)d_in[8];
    const float* gw1  = (const float*)d_in[9];
    const float* gb1  = (const float*)d_in[10];
    const float* gw2  = (const float*)d_in[11];
    const float* gb2  = (const float*)d_in[12];
    const float* fcw  = (const float*)d_in[13];
    const float* fcb  = (const float*)d_in[14];
    float* out = (float*)d_out;

    // edge features
    k_xaxb<<<BB*NN, 64>>>(x, ew1);
    k_edge<<<dim3(NN/32, NN/32, BB), dim3(32, 8)>>>(ew2, eb1, eb2);
    k_apred<<<dim3(NN/32, NN/32, BB), dim3(32, 8)>>>(mask);

    // laplacians
    k_colsum<<<dim3(NN/32, BB), dim3(32, 8)>>>(A, 0);
    k_colsum<<<dim3(NN/32, BB), dim3(32, 8)>>>(A, 1);
    k_scaleL<<<(BB*NN*NN)/256, 256>>>(A, 0);
    k_scaleL<<<(BB*NN*NN)/256, 256>>>(A, 1);

    // GCN layer 0: F=256, K=512
    k_gemm_LH<<<dim3(CC/64, NN/64, BB*2), 256>>>(x, 0, CC);
    k_gemm_W <<<dim3((BB*NN)/64), 256>>>(gw0, gb0, mask, 0, 2*CC);   // -> g_h0

    // GCN layer 1: F=64, K=128
    k_gemm_LH<<<dim3(1, NN/64, BB*2), 256>>>(x, 1, F0);
    k_gemm_W <<<dim3((BB*NN)/64), 256>>>(gw1, gb1, mask, 1, 2*F0);   // -> g_h1

    // GCN layer 2: F=64, K=128
    k_gemm_LH<<<dim3(1, NN/64, BB*2), 256>>>(x, 2, F0);
    k_gemm_W <<<dim3((BB*NN)/64), 256>>>(gw2, gb2, mask, 0, 2*F0);   // -> g_h0

    // max-pool + fc
    k_final<<<BB, 64>>>(fcw, fcb, out);

    (void)in_sizes; (void)n_in; (void)out_size;
}